// round 13
// baseline (speedup 1.0000x reference)
#include <cuda_runtime.h>
#include <cuda_fp16.h>
#include <cuda_bf16.h>
#include <math.h>
#include <stdint.h>

// Problem constants
#define NNODE 50000
#define NEDGE 800000
#define FIN 128
#define COUT 128   // NH*FOUT
#define NH 4

#define SCAN_BLK 1024
#define NSCAN_BLKS ((NNODE + SCAN_BLK - 1) / SCAN_BLK)   // 49

#define TILE_M 128
#define NTILES ((NNODE + TILE_M - 1) / TILE_M)           // 391
#define LDB 136   // bf16 elems per B row: 272 B (16-aligned)
#define LDE 132   // f32 elems per epilogue row (8B-aligned ops only)

// ---------------- device scratch (no allocations allowed) ----------------
// g_count is zero at module load; agg restores it to zero each call.
__device__ __half g_src_proj_h[NNODE * COUT];      // 12.8 MB (fp16)
__device__ float4 g_scores_src[NNODE];
__device__ float4 g_scores_trg[NNODE];
__device__ int    g_count[NNODE];
__device__ int    g_offsets[NNODE + 1];
__device__ int    g_blocksum[NSCAN_BLKS];
__device__ int    g_sorted_si[NEDGE];
__device__ float  g_Vt[FIN * NH];
// Ws^T split-bf16, k-permuted into mma-fragment-pair order: [n][perm(k)]
__device__ __align__(16) __nv_bfloat16 g_BhiT[COUT * FIN];
__device__ __align__(16) __nv_bfloat16 g_BloT[COUT * FIN];

// ---------------- small kernels ----------------

// Vt[f,h] = sum_j Wt[f, h*32+j] * a_trg[h, j]
__global__ void fold_kernel(const float* __restrict__ Wt,
                            const float* __restrict__ a_trg) {
    int f = threadIdx.x;
    #pragma unroll
    for (int h = 0; h < NH; h++) {
        float s = 0.0f;
        #pragma unroll
        for (int j = 0; j < 32; j++)
            s += Wt[f * COUT + h * 32 + j] * a_trg[h * 32 + j];
        g_Vt[f * NH + h] = s;
    }
}

// B = Ws^T split bf16 (hi/lo), k-index permuted so one LDS.64 yields a full
// m16n8k16 B fragment
__global__ void prepB_kernel(const float* __restrict__ Ws) {
    int t = blockIdx.x * blockDim.x + threadIdx.x;
    if (t >= FIN * COUT) return;
    int n = t >> 7;           // output col (B row)
    int k = t & 127;          // input feature
    float x = Ws[k * COUT + n];
    __nv_bfloat16 hi = __float2bfloat16(x);
    __nv_bfloat16 lo = __float2bfloat16(x - __bfloat162float(hi));
    int kt = k >> 4, r = k & 15;
    int pk = kt * 16 + ((r & 7) >> 1) * 4 + (r >> 3) * 2 + (r & 1);
    g_BhiT[n * FIN + pk] = hi;
    g_BloT[n * FIN + pk] = lo;
}

// scores_trg = trg @ Vt   (warp per node)
__global__ void strg_kernel(const float* __restrict__ trg) {
    __shared__ float Vsh[FIN * NH];
    for (int i = threadIdx.x; i < FIN * NH; i += blockDim.x) Vsh[i] = g_Vt[i];
    __syncthreads();

    int gwarp = (blockIdx.x * blockDim.x + threadIdx.x) >> 5;
    int lane = threadIdx.x & 31;
    if (gwarp >= NNODE) return;

    float4 xv = ((const float4*)(trg + (size_t)gwarp * FIN))[lane];
    int f0 = lane * 4;
    float a0, a1, a2, a3;
    a0 = xv.x * Vsh[(f0+0)*4+0] + xv.y * Vsh[(f0+1)*4+0] + xv.z * Vsh[(f0+2)*4+0] + xv.w * Vsh[(f0+3)*4+0];
    a1 = xv.x * Vsh[(f0+0)*4+1] + xv.y * Vsh[(f0+1)*4+1] + xv.z * Vsh[(f0+2)*4+1] + xv.w * Vsh[(f0+3)*4+1];
    a2 = xv.x * Vsh[(f0+0)*4+2] + xv.y * Vsh[(f0+1)*4+2] + xv.z * Vsh[(f0+2)*4+2] + xv.w * Vsh[(f0+3)*4+2];
    a3 = xv.x * Vsh[(f0+0)*4+3] + xv.y * Vsh[(f0+1)*4+3] + xv.z * Vsh[(f0+2)*4+3] + xv.w * Vsh[(f0+3)*4+3];
    #pragma unroll
    for (int o = 16; o > 0; o >>= 1) {
        a0 += __shfl_xor_sync(0xffffffffu, a0, o);
        a1 += __shfl_xor_sync(0xffffffffu, a1, o);
        a2 += __shfl_xor_sync(0xffffffffu, a2, o);
        a3 += __shfl_xor_sync(0xffffffffu, a3, o);
    }
    if (lane == 0) g_scores_trg[gwarp] = make_float4(a0, a1, a2, a3);
}

// ---------------- mma.sync split-bf16 projection ----------------

__device__ __forceinline__ void mma16816(float* c, const uint32_t* a,
                                         uint32_t b0, uint32_t b1) {
    asm volatile(
        "mma.sync.aligned.m16n8k16.row.col.f32.bf16.bf16.f32 "
        "{%0,%1,%2,%3}, {%4,%5,%6,%7}, {%8,%9}, {%0,%1,%2,%3};"
        : "+f"(c[0]), "+f"(c[1]), "+f"(c[2]), "+f"(c[3])
        : "r"(a[0]), "r"(a[1]), "r"(a[2]), "r"(a[3]), "r"(b0), "r"(b1));
}

__device__ __forceinline__ void split2(float2 v, uint32_t& hi, uint32_t& lo) {
    __nv_bfloat162 h = __floats2bfloat162_rn(v.x, v.y);
    float hx = __bfloat162float(__low2bfloat16(h));
    float hy = __bfloat162float(__high2bfloat16(h));
    __nv_bfloat162 l = __floats2bfloat162_rn(v.x - hx, v.y - hy);
    hi = *(uint32_t*)&h;
    lo = *(uint32_t*)&l;
}

#define SM_BHI 0
#define SM_BLO 34816
#define SM_ASH 69632
#define PROJ_SMEM (SM_ASH + 512)

__global__ void __launch_bounds__(256)
proj_mma_kernel(const float* __restrict__ src,
                const float* __restrict__ a_src) {
    extern __shared__ char smem[];
    __nv_bfloat16* sBhi = (__nv_bfloat16*)(smem + SM_BHI);
    __nv_bfloat16* sBlo = (__nv_bfloat16*)(smem + SM_BLO);
    float* ash = (float*)(smem + SM_ASH);

    int tid = threadIdx.x;
    int w = tid >> 5;
    int lane = tid & 31;
    int n0 = blockIdx.x * TILE_M;

    {
        const uint4* bh = (const uint4*)g_BhiT;
        const uint4* bl = (const uint4*)g_BloT;
        for (int i = tid; i < COUT * 16; i += 256) {
            int n = i >> 4, kk = (i & 15) * 8;
            *(uint4*)(sBhi + n * LDB + kk) = bh[i];
            *(uint4*)(sBlo + n * LDB + kk) = bl[i];
        }
        for (int i = tid; i < COUT; i += 256) ash[i] = a_src[i];
    }
    __syncthreads();

    int gID = lane >> 2;        // 0..7
    int tig = lane & 3;         // 0..3
    int m0 = n0 + w * 16 + gID;
    int m1 = m0 + 8;
    bool v0 = m0 < NNODE, v1 = m1 < NNODE;
    const float* row0 = src + (size_t)m0 * FIN;
    const float* row1 = src + (size_t)m1 * FIN;

    float acc[16][4];
    #pragma unroll
    for (int nt = 0; nt < 16; nt++) {
        acc[nt][0] = 0.f; acc[nt][1] = 0.f; acc[nt][2] = 0.f; acc[nt][3] = 0.f;
    }

    #pragma unroll
    for (int kt = 0; kt < 8; kt++) {
        int k0 = kt * 16 + tig * 2;
        float2 z = make_float2(0.f, 0.f);
        float2 L0 = v0 ? *(const float2*)(row0 + k0) : z;
        float2 L1 = v1 ? *(const float2*)(row1 + k0) : z;
        float2 L2 = v0 ? *(const float2*)(row0 + k0 + 8) : z;
        float2 L3 = v1 ? *(const float2*)(row1 + k0 + 8) : z;

        uint32_t ahi[4], alo[4];
        split2(L0, ahi[0], alo[0]);
        split2(L1, ahi[1], alo[1]);
        split2(L2, ahi[2], alo[2]);
        split2(L3, ahi[3], alo[3]);

        int kb = kt * 16 + tig * 4;
        #pragma unroll
        for (int nt = 0; nt < 16; nt++) {
            int n = nt * 8 + gID;
            uint2 bh = *(const uint2*)(sBhi + n * LDB + kb);
            uint2 bl = *(const uint2*)(sBlo + n * LDB + kb);
            mma16816(acc[nt], ahi, bh.x, bh.y);
            mma16816(acc[nt], ahi, bl.x, bl.y);
            mma16816(acc[nt], alo, bh.x, bh.y);
        }
    }

    __syncthreads();
    float* epi = (float*)(smem + w * (16 * LDE * 4));
    #pragma unroll
    for (int nt = 0; nt < 16; nt++) {
        int cb = nt * 8 + tig * 2;
        *(float2*)(epi + gID * LDE + cb)       = make_float2(acc[nt][0], acc[nt][1]);
        *(float2*)(epi + (gID + 8) * LDE + cb) = make_float2(acc[nt][2], acc[nt][3]);
    }
    __syncwarp();

    {
        int row = lane >> 1;
        int half = lane & 1;
        int m = n0 + w * 16 + row;
        if (m < NNODE) {
            const float* v = epi + row * LDE + half * 64;
            float p0 = 0.f, p1 = 0.f;
            #pragma unroll
            for (int j = 0; j < 32; j++) {
                p0 += v[j]      * ash[half * 64 + j];
                p1 += v[32 + j] * ash[half * 64 + 32 + j];
            }
            ((float2*)&g_scores_src[m])[half] = make_float2(p0, p1);

            uint32_t pk[16], pk2[16];
            #pragma unroll
            for (int j = 0; j < 16; j++) {
                __half2 h = __floats2half2_rn(v[2*j], v[2*j+1]);
                pk[j] = *(uint32_t*)&h;
            }
            #pragma unroll
            for (int j = 0; j < 16; j++) {
                __half2 h = __floats2half2_rn(v[32 + 2*j], v[32 + 2*j+1]);
                pk2[j] = *(uint32_t*)&h;
            }
            uint4* dst = (uint4*)(g_src_proj_h + (size_t)m * COUT + half * 64);
            #pragma unroll
            for (int q = 0; q < 4; q++)
                dst[q] = make_uint4(pk[q*4], pk[q*4+1], pk[q*4+2], pk[q*4+3]);
            #pragma unroll
            for (int q = 0; q < 4; q++)
                dst[4 + q] = make_uint4(pk2[q*4], pk2[q*4+1], pk2[q*4+2], pk2[q*4+3]);
        }
    }
}

// ---------------- edge pipeline ----------------

// pass 1: degree counts only (REDG — return value unused)
__global__ void edge1_kernel(const int* __restrict__ ei) {
    int e = blockIdx.x * blockDim.x + threadIdx.x;
    if (e >= NEDGE) return;
    int ti = ei[NEDGE + e];
    atomicAdd(&g_count[ti], 1);
}

// warp-shfl block scan: inclusive per block, writes offsets[gi+1] + blocksum
__global__ void scanA_kernel() {
    __shared__ int ws[32];
    int tid = threadIdx.x;
    int lane = tid & 31;
    int wid = tid >> 5;
    int gi = blockIdx.x * SCAN_BLK + tid;
    int v = (gi < NNODE) ? g_count[gi] : 0;

    int iv = v;
    #pragma unroll
    for (int o = 1; o < 32; o <<= 1) {
        int t = __shfl_up_sync(0xffffffffu, iv, o);
        if (lane >= o) iv += t;
    }
    if (lane == 31) ws[wid] = iv;
    __syncthreads();
    if (wid == 0) {
        int wv = ws[lane];
        int wiv = wv;
        #pragma unroll
        for (int o = 1; o < 32; o <<= 1) {
            int t = __shfl_up_sync(0xffffffffu, wiv, o);
            if (lane >= o) wiv += t;
        }
        ws[lane] = wiv - wv;   // exclusive warp base
    }
    __syncthreads();
    int total = iv + ws[wid];
    if (gi < NNODE) g_offsets[gi + 1] = total;
    if (tid == SCAN_BLK - 1) g_blocksum[blockIdx.x] = total;
}

// fused carry: each block reduces its own carry from blocksums, adds it
__global__ void scanBC_kernel() {
    __shared__ int s_carry;
    int b = blockIdx.x;
    int tid = threadIdx.x;
    if (tid < 32) {
        int c0 = (tid < b) ? g_blocksum[tid] : 0;
        int c1 = (32 + tid < b) ? g_blocksum[32 + tid] : 0;
        int s = c0 + c1;
        #pragma unroll
        for (int o = 16; o > 0; o >>= 1)
            s += __shfl_xor_sync(0xffffffffu, s, o);
        if (tid == 0) s_carry = s;
    }
    __syncthreads();
    int gi = b * SCAN_BLK + tid;
    if (b == 0) {
        if (tid == 0) g_offsets[0] = 0;
        return;   // carry 0
    }
    if (gi < NNODE) g_offsets[gi + 1] += s_carry;
}

// pass 2: permute source ids into CSR order. Rank comes from incrementing
// the offsets array itself: afterwards g_offsets[t] == old offsets[t+1].
__global__ void edge2_kernel(const int* __restrict__ ei) {
    int e = blockIdx.x * blockDim.x + threadIdx.x;
    if (e >= NEDGE) return;
    int si = ei[e];
    int ti = ei[NEDGE + e];
    int pos = atomicAdd(&g_offsets[ti], 1);
    g_sorted_si[pos] = si;
}

// aggregation: warp per target node. Lane l owns output cols 4l..4l+3
// (head = l>>3). Reads SHIFTED offsets (post-edge2). Restores g_count=0.
__global__ void agg_kernel(float* __restrict__ out) {
    int gwarp = (blockIdx.x * blockDim.x + threadIdx.x) >> 5;
    int lane = threadIdx.x & 31;
    if (gwarp >= NNODE) return;

    int s = (gwarp > 0) ? g_offsets[gwarp - 1] : 0;
    int e2 = g_offsets[gwarp];
    if (lane == 0) g_count[gwarp] = 0;   // restore invariant for next call

    int h = lane >> 3;
    const float* ssf = (const float*)g_scores_src;
    const uint2* rows = (const uint2*)g_src_proj_h;   // 32 uint2 per row
    float stH = ((const float*)g_scores_trg)[gwarp * 4 + h];

    float a0 = 0.f, a1 = 0.f, a2 = 0.f, a3 = 0.f, d = 0.f;

    for (int i = s; i < e2; i += 8) {
        int sidx[8];
        bool m[8];
        #pragma unroll
        for (int q = 0; q < 8; q++) {
            m[q] = (i + q < e2);
            sidx[q] = m[q] ? g_sorted_si[i + q] : g_sorted_si[i];
        }
        float sc[8];
        uint2 v[8];
        #pragma unroll
        for (int q = 0; q < 8; q++) {
            sc[q] = ssf[sidx[q] * 4 + h];
            v[q] = rows[(size_t)sidx[q] * 32 + lane];
        }
        #pragma unroll
        for (int q = 0; q < 8; q++) {
            float sv = sc[q] + stH;
            float w = m[q] ? __expf(fmaxf(sv, 0.2f * sv)) : 0.f;
            float2 f0 = __half22float2(*(__half2*)&v[q].x);
            float2 f1 = __half22float2(*(__half2*)&v[q].y);
            a0 += w * f0.x; a1 += w * f0.y;
            a2 += w * f1.x; a3 += w * f1.y;
            d += w;
        }
    }

    float r = 1.0f / (d + 1e-16f);
    ((float4*)(out + (size_t)gwarp * COUT))[lane] =
        make_float4(a0 * r, a1 * r, a2 * r, a3 * r);
}

// ---------------- launch ----------------

extern "C" void kernel_launch(void* const* d_in, const int* in_sizes, int n_in,
                              void* d_out, int out_size) {
    const float* trg   = (const float*)d_in[0];
    const float* src   = (const float*)d_in[1];
    const int*   ei    = (const int*)d_in[2];
    const float* Wt    = (const float*)d_in[3];
    const float* Ws    = (const float*)d_in[4];
    const float* a_src = (const float*)d_in[5];
    const float* a_trg = (const float*)d_in[6];
    float* out = (float*)d_out;

    static cudaStream_t s1 = nullptr, s2 = nullptr;
    static cudaEvent_t evFork = nullptr, evJoin1 = nullptr, evJoin2 = nullptr;
    if (s1 == nullptr) {
        cudaStreamCreateWithFlags(&s1, cudaStreamNonBlocking);
        cudaStreamCreateWithFlags(&s2, cudaStreamNonBlocking);
        cudaEventCreateWithFlags(&evFork, cudaEventDisableTiming);
        cudaEventCreateWithFlags(&evJoin1, cudaEventDisableTiming);
        cudaEventCreateWithFlags(&evJoin2, cudaEventDisableTiming);
    }

    cudaFuncSetAttribute(proj_mma_kernel,
                         cudaFuncAttributeMaxDynamicSharedMemorySize, PROJ_SMEM);

    // fork
    cudaEventRecord(evFork, 0);
    cudaStreamWaitEvent(s1, evFork, 0);
    cudaStreamWaitEvent(s2, evFork, 0);

    // branch 1 (s1): CSR build — depends only on ei (+ zeroed counts,
    // maintained as an invariant by agg)
    {
        int blocks = (NEDGE + 255) / 256;
        edge1_kernel<<<blocks, 256, 0, s1>>>(ei);
    }
    scanA_kernel<<<NSCAN_BLKS, SCAN_BLK, 0, s1>>>();
    scanBC_kernel<<<NSCAN_BLKS, SCAN_BLK, 0, s1>>>();
    {
        int blocks = (NEDGE + 255) / 256;
        edge2_kernel<<<blocks, 256, 0, s1>>>(ei);
    }
    cudaEventRecord(evJoin1, s1);

    // branch 2 (s2): fold -> strg
    fold_kernel<<<1, 128, 0, s2>>>(Wt, a_trg);
    {
        int blocks = (NNODE * 32 + 255) / 256;
        strg_kernel<<<blocks, 256, 0, s2>>>(trg);
    }
    cudaEventRecord(evJoin2, s2);

    // branch 0 (default): prepB -> tensor proj
    prepB_kernel<<<64, 256>>>(Ws);
    proj_mma_kernel<<<NTILES, 256, PROJ_SMEM>>>(src, a_src);

    // join all -> aggregate
    cudaStreamWaitEvent(0, evJoin1, 0);
    cudaStreamWaitEvent(0, evJoin2, 0);
    {
        int blocks = (NNODE * 32 + 255) / 256;
        agg_kernel<<<blocks, 256>>>(out);
    }
}